// round 6
// baseline (speedup 1.0000x reference)
#include <cuda_runtime.h>
#include <cuda_fp16.h>
#include <math.h>
#include <stdint.h>

// Problem constants
#define BQ   2
#define SEQ  2048
#define DIM  1024
#define NH   16
#define HDIM 64
#define MROWS (BQ * SEQ)   // 4096

#define C63 0.984375f      // 63/64
#define CINV64 0.015625f   // 1/64

// Scratch (device globals). h = fp16 main, m = fp16 merged-residual.
__device__ __half gXh[MROWS * DIM];
__device__ __half gXm[MROWS * DIM];
__device__ __half gWh[4 * DIM * DIM];
__device__ __half gWm[4 * DIM * DIM];
__device__ __half gQh[MROWS * DIM];
__device__ __half gQm[MROWS * DIM];
__device__ __half gKh[MROWS * DIM];
__device__ __half gKm[MROWS * DIM];
__device__ __half gVh[MROWS * DIM];
__device__ __half gVm[MROWS * DIM];
__device__ __half gOh[MROWS * DIM];
__device__ __half gOm[MROWS * DIM];

// ---------------------------------------------------------------------------
// Helpers
// ---------------------------------------------------------------------------
__device__ __forceinline__ uint32_t smem_u32(const void* p) {
    uint32_t a;
    asm("{ .reg .u64 t; cvta.to.shared.u64 t, %1; cvt.u32.u64 %0, t; }"
        : "=r"(a) : "l"(p));
    return a;
}
__device__ __forceinline__ void cp16(uint32_t dst, const void* src) {
    asm volatile("cp.async.cg.shared.global [%0], [%1], 16;"
                 :: "r"(dst), "l"(__cvta_generic_to_global(src)));
}
__device__ __forceinline__ void cp_commit() {
    asm volatile("cp.async.commit_group;" ::: "memory");
}
__device__ __forceinline__ void ldsm4(uint32_t* r, uint32_t addr) {
    asm volatile("ldmatrix.sync.aligned.m8n8.x4.shared.b16 {%0,%1,%2,%3}, [%4];"
                 : "=r"(r[0]), "=r"(r[1]), "=r"(r[2]), "=r"(r[3]) : "r"(addr));
}
__device__ __forceinline__ void ldsm4t(uint32_t* r, uint32_t addr) {
    asm volatile("ldmatrix.sync.aligned.m8n8.x4.trans.shared.b16 {%0,%1,%2,%3}, [%4];"
                 : "=r"(r[0]), "=r"(r[1]), "=r"(r[2]), "=r"(r[3]) : "r"(addr));
}
// fp32-accumulator MMA
__device__ __forceinline__ void mma16816(float* c, const uint32_t* a, const uint32_t* b) {
    asm volatile(
        "mma.sync.aligned.m16n8k16.row.col.f32.f16.f16.f32 "
        "{%0,%1,%2,%3}, {%4,%5,%6,%7}, {%8,%9}, {%0,%1,%2,%3};"
        : "+f"(c[0]), "+f"(c[1]), "+f"(c[2]), "+f"(c[3])
        : "r"(a[0]), "r"(a[1]), "r"(a[2]), "r"(a[3]), "r"(b[0]), "r"(b[1]));
}
// fp16-accumulator MMA (for the /64-scale residual term)
__device__ __forceinline__ void mma16816h(uint32_t* c, const uint32_t* a, const uint32_t* b) {
    asm volatile(
        "mma.sync.aligned.m16n8k16.row.col.f16.f16.f16.f16 "
        "{%0,%1}, {%2,%3,%4,%5}, {%6,%7}, {%0,%1};"
        : "+r"(c[0]), "+r"(c[1])
        : "r"(a[0]), "r"(a[1]), "r"(a[2]), "r"(a[3]), "r"(b[0]), "r"(b[1]));
}
__device__ __forceinline__ uint32_t pack_h2(__half a, __half b) {
    __half2 t = __halves2half2(a, b);
    return *(uint32_t*)&t;
}
__device__ __forceinline__ float h2lo(uint32_t u) {
    return __low2float(*(__half2*)&u);
}
__device__ __forceinline__ float h2hi(uint32_t u) {
    return __high2float(*(__half2*)&u);
}
// A-side split: h = fp16(x), m = fp16(h + 64*(x-h))
__device__ __forceinline__ void splitA(float f0, float f1, uint32_t& h, uint32_t& m) {
    __half h0 = __float2half_rn(f0), h1 = __float2half_rn(f1);
    float r0 = f0 - __half2float(h0), r1 = f1 - __half2float(h1);
    __half m0 = __float2half_rn(fmaf(64.f, r0, __half2float(h0)));
    __half m1 = __float2half_rn(fmaf(64.f, r1, __half2float(h1)));
    h = pack_h2(h0, h1);
    m = pack_h2(m0, m1);
}
// B-side split: h = fp16(x), m = fp16((x-h) + h/64)
__device__ __forceinline__ void splitB(float f0, float f1, uint32_t& h, uint32_t& m) {
    __half h0 = __float2half_rn(f0), h1 = __float2half_rn(f1);
    float r0 = f0 - __half2float(h0), r1 = f1 - __half2float(h1);
    __half m0 = __float2half_rn(fmaf(__half2float(h0), CINV64, r0));
    __half m1 = __float2half_rn(fmaf(__half2float(h1), CINV64, r1));
    h = pack_h2(h0, h1);
    m = pack_h2(m0, m1);
}

// ---------------------------------------------------------------------------
// Convert fp32 inputs -> fp16 h/m pairs. X: A-side. Weights: B-side.
// ---------------------------------------------------------------------------
__global__ __launch_bounds__(256) void convert_inputs(
    const float* __restrict__ X, const float* __restrict__ Wq,
    const float* __restrict__ Wk, const float* __restrict__ Wv,
    const float* __restrict__ Wo) {
    const int XQ = MROWS * DIM / 4;
    const int WQ = DIM * DIM / 4;
    const int total4 = XQ + 4 * WQ;
    for (int i = blockIdx.x * blockDim.x + threadIdx.x; i < total4;
         i += gridDim.x * blockDim.x) {
        const float* src;
        __half *dh, *dm;
        bool aside;
        if (i < XQ) {
            int e = i * 4;
            src = X + e; dh = gXh + e; dm = gXm + e; aside = true;
        } else {
            int t = i - XQ;
            int w = t / WQ;
            int off = (t - w * WQ) * 4;
            src = (w == 0) ? Wq + off : (w == 1) ? Wk + off
                  : (w == 2) ? Wv + off : Wo + off;
            dh = gWh + (size_t)w * DIM * DIM + off;
            dm = gWm + (size_t)w * DIM * DIM + off;
            aside = false;
        }
        float4 v = *(const float4*)src;
        uint32_t h0, m0, h1, m1;
        if (aside) {
            splitA(v.x, v.y, h0, m0);
            splitA(v.z, v.w, h1, m1);
        } else {
            splitB(v.x, v.y, h0, m0);
            splitB(v.z, v.w, h1, m1);
        }
        ((uint32_t*)dh)[0] = h0;
        ((uint32_t*)dh)[1] = h1;
        ((uint32_t*)dm)[0] = m0;
        ((uint32_t*)dm)[1] = m1;
    }
}

// ---------------------------------------------------------------------------
// Tensor-core GEMM (merged 2-MMA fp16, residual in fp16 accumulator):
// 128x128 CTA tile, K-step 32, 512 threads = 16 warps (4m x 4n, 32x32 each),
// 3-stage cp.async. Result: C = C1*(63/64) + C2.
// ---------------------------------------------------------------------------
#define STAGE_BYTES 32768
#define SM_BH 16384
#define SM_BM 24576
#define GEMM_SMEM (3 * STAGE_BYTES)

__device__ __forceinline__ void gemm_fill(uint32_t sbuf,
                                          const __half* __restrict__ Ah,
                                          const __half* __restrict__ Am,
                                          const __half* __restrict__ Bh,
                                          const __half* __restrict__ Bm,
                                          int row0, int col0, int kt, int tid) {
#pragma unroll
    for (int i = 0; i < 2; ++i) {  // A: 1024 16B chunks (h: c<4, m: c>=4)
        int lin = tid + i * 512;
        int m = lin >> 3, c = lin & 7;
        const __half* src =
            ((c < 4) ? Ah : Am) + (size_t)(row0 + m) * DIM + kt + (c & 3) * 8;
        uint32_t dst = sbuf + m * 128 + ((c ^ (m & 7)) << 4);
        cp16(dst, src);
    }
#pragma unroll
    for (int i = 0; i < 2; ++i) {  // B: 1024 16B chunks (h + m tiles)
        int lin = tid + i * 512;
        int tile = lin >> 9, rem = lin & 511;
        int k = rem >> 4, c = rem & 15;
        const __half* src =
            (tile ? Bm : Bh) + (size_t)(kt + k) * DIM + col0 + c * 8;
        uint32_t dst = sbuf + (tile ? SM_BM : SM_BH) + k * 256 +
                       ((c >> 3) << 7) + (((c & 7) ^ (k & 7)) << 4);
        cp16(dst, src);
    }
}

__device__ __forceinline__ void mma_gemm_body(
    const __half* __restrict__ Ah_g, const __half* __restrict__ Am_g,
    const __half* __restrict__ Bh_g, const __half* __restrict__ Bm_g,
    const float* __restrict__ bias, float* __restrict__ Yf,
    __half* __restrict__ Yh, __half* __restrict__ Ym, int aside_out) {
    extern __shared__ __align__(1024) char smem[];
    const uint32_t sb = smem_u32(smem);
    const int tid = threadIdx.x;
    const int row0 = blockIdx.y * 128, col0 = blockIdx.x * 128;
    const int lane = tid & 31, wid = tid >> 5;
    const int wm = wid & 3, wn = wid >> 2;   // 4m x 4n warps, 32x32 tiles
    const int q = lane >> 3, r = lane & 7;
    const int arow = (q & 1) * 8 + r;
    const int aq = q >> 1;

    float acc1[2][4][4];      // fp32 main accumulators (2 mt x 4 nt)
    uint32_t acc2[2][4][2];   // fp16 packed residual accumulators
#pragma unroll
    for (int mt = 0; mt < 2; ++mt)
#pragma unroll
        for (int nt = 0; nt < 4; ++nt) {
#pragma unroll
            for (int e = 0; e < 4; ++e) acc1[mt][nt][e] = 0.f;
            acc2[mt][nt][0] = 0u;
            acc2[mt][nt][1] = 0u;
        }

    gemm_fill(sb, Ah_g, Am_g, Bh_g, Bm_g, row0, col0, 0, tid);
    cp_commit();
    gemm_fill(sb + STAGE_BYTES, Ah_g, Am_g, Bh_g, Bm_g, row0, col0, 32, tid);
    cp_commit();

    for (int s = 0; s < 32; ++s) {
        const int buf = s % 3;
        if (s + 2 < 32) {
            gemm_fill(sb + ((s + 2) % 3) * STAGE_BYTES, Ah_g, Am_g, Bh_g, Bm_g,
                      row0, col0, (s + 2) * 32, tid);
            cp_commit();
            asm volatile("cp.async.wait_group 2;" ::: "memory");
        } else if (s + 1 < 32) {
            asm volatile("cp.async.wait_group 1;" ::: "memory");
        } else {
            asm volatile("cp.async.wait_group 0;" ::: "memory");
        }
        __syncthreads();

        const uint32_t sA = sb + buf * STAGE_BYTES;
        const uint32_t sBh = sA + SM_BH;
        const uint32_t sBm = sA + SM_BM;

#pragma unroll
        for (int k16 = 0; k16 < 2; ++k16) {
            uint32_t bh[8], bm[8];
            {
                const int krow = k16 * 16 + (q & 1) * 8 + r;
#pragma unroll
                for (int g2 = 0; g2 < 2; ++g2) {
                    int cg = wn * 4 + g2 * 2 + (q >> 1);
                    uint32_t baddr = krow * 256 + ((cg >> 3) << 7) +
                                     (((cg & 7) ^ (krow & 7)) << 4);
                    ldsm4t(&bh[g2 * 4], sBh + baddr);
                    ldsm4t(&bm[g2 * 4], sBm + baddr);
                }
            }
            uint32_t ah[2][4], am[2][4];
#pragma unroll
            for (int mt = 0; mt < 2; ++mt) {
                int row = wm * 32 + mt * 16 + arow;
                int c1 = k16 * 2 + aq;
                int c2 = 4 + k16 * 2 + aq;
                ldsm4(ah[mt], sA + row * 128 + ((c1 ^ r) << 4));
                ldsm4(am[mt], sA + row * 128 + ((c2 ^ r) << 4));
            }
#pragma unroll
            for (int mt = 0; mt < 2; ++mt)
#pragma unroll
                for (int nt = 0; nt < 4; ++nt) {
                    const uint32_t* bph = &bh[(nt >> 1) * 4 + (nt & 1) * 2];
                    const uint32_t* bpm = &bm[(nt >> 1) * 4 + (nt & 1) * 2];
                    mma16816(acc1[mt][nt], ah[mt], bph);
                    mma16816h(acc2[mt][nt], am[mt], bpm);
                }
        }
        __syncthreads();
    }

    const int cg = lane >> 2, ct = lane & 3;
#pragma unroll
    for (int mt = 0; mt < 2; ++mt) {
        int r0 = row0 + wm * 32 + mt * 16 + cg;
#pragma unroll
        for (int nt = 0; nt < 4; ++nt) {
            int col = col0 + wn * 32 + nt * 8 + ct * 2;
            float b0 = bias ? bias[col] : 0.f;
            float b1 = bias ? bias[col + 1] : 0.f;
            float v00 = fmaf(acc1[mt][nt][0], C63, h2lo(acc2[mt][nt][0])) + b0;
            float v01 = fmaf(acc1[mt][nt][1], C63, h2hi(acc2[mt][nt][0])) + b1;
            float v10 = fmaf(acc1[mt][nt][2], C63, h2lo(acc2[mt][nt][1])) + b0;
            float v11 = fmaf(acc1[mt][nt][3], C63, h2hi(acc2[mt][nt][1])) + b1;
            if (Yf) {
                *(float2*)(Yf + (size_t)r0 * DIM + col) = make_float2(v00, v01);
                *(float2*)(Yf + (size_t)(r0 + 8) * DIM + col) = make_float2(v10, v11);
            } else {
                uint32_t h, m;
                if (aside_out) splitA(v00, v01, h, m); else splitB(v00, v01, h, m);
                *(uint32_t*)&Yh[(size_t)r0 * DIM + col] = h;
                *(uint32_t*)&Ym[(size_t)r0 * DIM + col] = m;
                if (aside_out) splitA(v10, v11, h, m); else splitB(v10, v11, h, m);
                *(uint32_t*)&Yh[(size_t)(r0 + 8) * DIM + col] = h;
                *(uint32_t*)&Ym[(size_t)(r0 + 8) * DIM + col] = m;
            }
        }
    }
}

__global__ __launch_bounds__(512, 1) void qkv_mma(const float* __restrict__ bq,
                                                  const float* __restrict__ bk) {
    const int z = blockIdx.z;
    const __half* Bh = gWh + (size_t)z * DIM * DIM;
    const __half* Bm = gWm + (size_t)z * DIM * DIM;
    const float* bias = (z == 0) ? bq : (z == 1) ? bk : nullptr;
    __half* Yh = (z == 0) ? gQh : (z == 1) ? gKh : gVh;
    __half* Ym = (z == 0) ? gQm : (z == 1) ? gKm : gVm;
    mma_gemm_body(gXh, gXm, Bh, Bm, bias, nullptr, Yh, Ym, z == 0 ? 1 : 0);
}

__global__ __launch_bounds__(512, 1) void out_mma(const float* __restrict__ bo,
                                                  float* __restrict__ out) {
    mma_gemm_body(gOh, gOm, gWh + (size_t)3 * DIM * DIM,
                  gWm + (size_t)3 * DIM * DIM, bo, out, nullptr, nullptr, 0);
}

// ---------------------------------------------------------------------------
// Flash attention on tensor cores (merged 2-MMA fp16) — unchanged from R5.
// ---------------------------------------------------------------------------
#define A_ST0 32768
#define A_STAGE 65536
#define ATTN_SMEM (32768 + 2 * 65536)

__global__ __launch_bounds__(256, 1) void attn_mma() {
    extern __shared__ __align__(1024) char smem[];
    const uint32_t sb = smem_u32(smem);
    const int tid = threadIdx.x;
    const int lane = tid & 31, w = tid >> 5;
    const int q = lane >> 3, r = lane & 7;
    const int g = lane >> 2, t = lane & 3;
    const int it = 15 - (int)blockIdx.x;  // heavy tiles first
    const int bh = blockIdx.y;
    const int b = bh >> 4, h = bh & 15;
    const int i0 = it * 128;
    const float slope = exp2f(-0.5f * (float)(h + 1));
    const int qrow_base = b * SEQ + i0;
    const int hcol = h * HDIM;

#pragma unroll
    for (int i = 0; i < 8; ++i) {
        int lin = tid + i * 256;
        int tz = lin >> 10;
        int rem = lin & 1023;
        int m = rem >> 3, c = rem & 7;
        const __half* src =
            (tz ? gQm : gQh) + (size_t)(qrow_base + m) * DIM + hcol + c * 8;
        cp16(sb + tz * 16384 + m * 128 + ((c ^ (m & 7)) << 4), src);
    }
    {
        const int krow_base = b * SEQ;
#pragma unroll
        for (int i = 0; i < 16; ++i) {
            int lin = tid + i * 256;
            int tz = lin >> 10;
            int rem = lin & 1023;
            int m = rem >> 3, c = rem & 7;
            const __half* src =
                ((tz == 0) ? gKh : (tz == 1) ? gKm : (tz == 2) ? gVh : gVm) +
                (size_t)(krow_base + m) * DIM + hcol + c * 8;
            cp16(sb + A_ST0 + tz * 16384 + m * 128 + ((c ^ (m & 7)) << 4), src);
        }
    }
    cp_commit();

    float o1[8][4], o2[8][4];
#pragma unroll
    for (int nt = 0; nt < 8; ++nt)
#pragma unroll
        for (int e = 0; e < 4; ++e) {
            o1[nt][e] = 0.f;
            o2[nt][e] = 0.f;
        }
    float m0 = -1e30f, m1 = -1e30f, l0 = 0.f, l1 = 0.f;
    uint32_t qh[4][4], qm[4][4];

    int buf = 0;
    for (int jt = 0; jt <= it; ++jt) {
        if (jt < it) {
            const int krow_base = b * SEQ + (jt + 1) * 128;
            const uint32_t st = sb + A_ST0 + (buf ^ 1) * A_STAGE;
#pragma unroll
            for (int i = 0; i < 16; ++i) {
                int lin = tid + i * 256;
                int tz = lin >> 10;
                int rem = lin & 1023;
                int m = rem >> 3, c = rem & 7;
                const __half* src =
                    ((tz == 0) ? gKh : (tz == 1) ? gKm : (tz == 2) ? gVh : gVm) +
                    (size_t)(krow_base + m) * DIM + hcol + c * 8;
                cp16(st + tz * 16384 + m * 128 + ((c ^ (m & 7)) << 4), src);
            }
            cp_commit();
            asm volatile("cp.async.wait_group 1;" ::: "memory");
        } else {
            asm volatile("cp.async.wait_group 0;" ::: "memory");
        }
        __syncthreads();

        if (jt == 0) {
#pragma unroll
            for (int k16 = 0; k16 < 4; ++k16) {
                int row = w * 16 + (q & 1) * 8 + r;
                int c = k16 * 2 + (q >> 1);
                uint32_t ad = sb + row * 128 + ((c ^ r) << 4);
                ldsm4(qh[k16], ad);
                ldsm4(qm[k16], ad + 16384);
            }
        }

        const uint32_t sk = sb + A_ST0 + buf * A_STAGE;
        const uint32_t sv = sk + 32768;

        float s[16][4];
#pragma unroll
        for (int nt16 = 0; nt16 < 8; ++nt16) {
            float s1[2][4], s2[2][4];
#pragma unroll
            for (int e = 0; e < 4; ++e) {
                s1[0][e] = s1[1][e] = 0.f;
                s2[0][e] = s2[1][e] = 0.f;
            }
            const int row = nt16 * 16 + (q >> 1) * 8 + r;
#pragma unroll
            for (int k16 = 0; k16 < 4; ++k16) {
                const int c = k16 * 2 + (q & 1);
                uint32_t ad = sk + row * 128 + ((c ^ r) << 4);
                uint32_t kh[4], km[4];
                ldsm4(kh, ad);
                ldsm4(km, ad + 16384);
                mma16816(s1[0], qh[k16], kh);
                mma16816(s2[0], qm[k16], km);
                mma16816(s1[1], qh[k16], kh + 2);
                mma16816(s2[1], qm[k16], km + 2);
            }
#pragma unroll
            for (int e = 0; e < 4; ++e) {
                s[2 * nt16][e] = fmaf(s1[0][e], C63, s2[0][e]);
                s[2 * nt16 + 1][e] = fmaf(s1[1][e], C63, s2[1][e]);
            }
        }

        const int j0 = jt * 128;
        const int rowg0 = i0 + w * 16 + g;
        const int rowg1 = rowg0 + 8;
        const bool diag = (jt == it);
        float mx0 = -1e30f, mx1 = -1e30f;
#pragma unroll
        for (int nt = 0; nt < 16; ++nt) {
            const int jc = j0 + nt * 8 + 2 * t;
            const float c0 = (float)jc;
            s[nt][0] = s[nt][0] * 0.125f - slope * c0;
            s[nt][1] = s[nt][1] * 0.125f - slope * (c0 + 1.f);
            s[nt][2] = s[nt][2] * 0.125f - slope * c0;
            s[nt][3] = s[nt][3] * 0.125f - slope * (c0 + 1.f);
            if (diag) {
                if (jc > rowg0) s[nt][0] = -1e30f;
                if (jc + 1 > rowg0) s[nt][1] = -1e30f;
                if (jc > rowg1) s[nt][2] = -1e30f;
                if (jc + 1 > rowg1) s[nt][3] = -1e30f;
            }
            mx0 = fmaxf(mx0, fmaxf(s[nt][0], s[nt][1]));
            mx1 = fmaxf(mx1, fmaxf(s[nt][2], s[nt][3]));
        }
        mx0 = fmaxf(mx0, __shfl_xor_sync(0xffffffffu, mx0, 1, 4));
        mx0 = fmaxf(mx0, __shfl_xor_sync(0xffffffffu, mx0, 2, 4));
        mx1 = fmaxf(mx1, __shfl_xor_sync(0xffffffffu, mx1, 1, 4));
        mx1 = fmaxf(mx1, __shfl_xor_sync(0xffffffffu, mx1, 2, 4));
        const float mn0 = fmaxf(m0, mx0), mn1 = fmaxf(m1, mx1);
        const float cr0 = __expf(m0 - mn0), cr1 = __expf(m1 - mn1);
        m0 = mn0;
        m1 = mn1;
        float sum0 = 0.f, sum1 = 0.f;
#pragma unroll
        for (int nt = 0; nt < 16; ++nt) {
            s[nt][0] = __expf(s[nt][0] - mn0);
            s[nt][1] = __expf(s[nt][1] - mn0);
            s[nt][2] = __expf(s[nt][2] - mn1);
            s[nt][3] = __expf(s[nt][3] - mn1);
            sum0 += s[nt][0] + s[nt][1];
            sum1 += s[nt][2] + s[nt][3];
        }
        sum0 += __shfl_xor_sync(0xffffffffu, sum0, 1, 4);
        sum0 += __shfl_xor_sync(0xffffffffu, sum0, 2, 4);
        sum1 += __shfl_xor_sync(0xffffffffu, sum1, 1, 4);
        sum1 += __shfl_xor_sync(0xffffffffu, sum1, 2, 4);
        l0 = l0 * cr0 + sum0;
        l1 = l1 * cr1 + sum1;
#pragma unroll
        for (int nt = 0; nt < 8; ++nt) {
            o1[nt][0] *= cr0; o1[nt][1] *= cr0;
            o1[nt][2] *= cr1; o1[nt][3] *= cr1;
            o2[nt][0] *= cr0; o2[nt][1] *= cr0;
            o2[nt][2] *= cr1; o2[nt][3] *= cr1;
        }

#pragma unroll
        for (int k16 = 0; k16 < 8; ++k16) {
            uint32_t ph[4], pm[4];
            splitA(s[2 * k16][0], s[2 * k16][1], ph[0], pm[0]);
            splitA(s[2 * k16][2], s[2 * k16][3], ph[1], pm[1]);
            splitA(s[2 * k16 + 1][0], s[2 * k16 + 1][1], ph[2], pm[2]);
            splitA(s[2 * k16 + 1][2], s[2 * k16 + 1][3], ph[3], pm[3]);
            const int row = k16 * 16 + (q & 1) * 8 + r;
#pragma unroll
            for (int cgp = 0; cgp < 4; ++cgp) {
                const int c = cgp * 2 + (q >> 1);
                uint32_t ad = sv + row * 128 + ((c ^ r) << 4);
                uint32_t vh[4], vm[4];
                ldsm4t(vh, ad);
                ldsm4t(vm, ad + 16384);
                mma16816(o1[cgp * 2], ph, vh);
                mma16816(o2[cgp * 2], pm, vm);
                mma16816(o1[cgp * 2 + 1], ph, vh + 2);
                mma16816(o2[cgp * 2 + 1], pm, vm + 2);
            }
        }
        __syncthreads();
        buf ^= 1;
    }

    const float inv0 = 1.f / l0, inv1 = 1.f / l1;
    const size_t orow0 = (size_t)(qrow_base + w * 16 + g) * DIM + hcol;
    const size_t orow1 = orow0 + (size_t)8 * DIM;
#pragma unroll
    for (int nt = 0; nt < 8; ++nt) {
        const int col = nt * 8 + 2 * t;
        float f0 = fmaf(o1[nt][0], C63, o2[nt][0]) * inv0;
        float f1 = fmaf(o1[nt][1], C63, o2[nt][1]) * inv0;
        float f2 = fmaf(o1[nt][2], C63, o2[nt][2]) * inv1;
        float f3 = fmaf(o1[nt][3], C63, o2[nt][3]) * inv1;
        uint32_t hh, mm;
        splitA(f0, f1, hh, mm);
        *(uint32_t*)&gOh[orow0 + col] = hh;
        *(uint32_t*)&gOm[orow0 + col] = mm;
        splitA(f2, f3, hh, mm);
        *(uint32_t*)&gOh[orow1 + col] = hh;
        *(uint32_t*)&gOm[orow1 + col] = mm;
    }
}

// ---------------------------------------------------------------------------
extern "C" void kernel_launch(void* const* d_in, const int* in_sizes, int n_in,
                              void* d_out, int out_size) {
    const float* X  = (const float*)d_in[0];
    const float* Wq = (const float*)d_in[1];
    const float* bq = (const float*)d_in[2];
    const float* Wk = (const float*)d_in[3];
    const float* bk = (const float*)d_in[4];
    const float* Wv = (const float*)d_in[5];
    const float* Wo = (const float*)d_in[6];
    const float* bo = (const float*)d_in[7];
    float* out = (float*)d_out;

    cudaFuncSetAttribute(qkv_mma, cudaFuncAttributeMaxDynamicSharedMemorySize, GEMM_SMEM);
    cudaFuncSetAttribute(out_mma, cudaFuncAttributeMaxDynamicSharedMemorySize, GEMM_SMEM);
    cudaFuncSetAttribute(attn_mma, cudaFuncAttributeMaxDynamicSharedMemorySize, ATTN_SMEM);

    convert_inputs<<<2048, 256>>>(X, Wq, Wk, Wv, Wo);
    qkv_mma<<<dim3(DIM / 128, MROWS / 128, 3), 512, GEMM_SMEM>>>(bq, bk);
    attn_mma<<<dim3(SEQ / 128, BQ * NH), 256, ATTN_SMEM>>>();
    out_mma<<<dim3(DIM / 128, MROWS / 128, 1), 512, GEMM_SMEM>>>(bo, out);
}

// round 7
// speedup vs baseline: 1.4025x; 1.4025x over previous
#include <cuda_runtime.h>
#include <cuda_fp16.h>
#include <math.h>
#include <stdint.h>

// Problem constants
#define BQ   2
#define SEQ  2048
#define DIM  1024
#define NH   16
#define HDIM 64
#define MROWS (BQ * SEQ)   // 4096

#define C63 0.984375f      // 63/64
#define CINV64 0.015625f   // 1/64

// Scratch. h = fp16 main, m = fp16 merged-residual (only where 2-term used).
__device__ __half gXh[MROWS * DIM];
__device__ __half gXm[MROWS * DIM];
__device__ __half gWh[4 * DIM * DIM];
__device__ __half gWm[4 * DIM * DIM];
__device__ __half gQh[MROWS * DIM];
__device__ __half gQm[MROWS * DIM];
__device__ __half gKh[MROWS * DIM];
__device__ __half gKm[MROWS * DIM];
__device__ __half gVh[MROWS * DIM];   // V single fp16 (quantized by PV anyway)
__device__ __half gOh[MROWS * DIM];   // attention output, single fp16

// ---------------------------------------------------------------------------
// Helpers
// ---------------------------------------------------------------------------
__device__ __forceinline__ uint32_t smem_u32(const void* p) {
    uint32_t a;
    asm("{ .reg .u64 t; cvta.to.shared.u64 t, %1; cvt.u32.u64 %0, t; }"
        : "=r"(a) : "l"(p));
    return a;
}
__device__ __forceinline__ void cp16(uint32_t dst, const void* src) {
    asm volatile("cp.async.cg.shared.global [%0], [%1], 16;"
                 :: "r"(dst), "l"(__cvta_generic_to_global(src)));
}
__device__ __forceinline__ void cp_commit() {
    asm volatile("cp.async.commit_group;" ::: "memory");
}
__device__ __forceinline__ void ldsm4(uint32_t* r, uint32_t addr) {
    asm volatile("ldmatrix.sync.aligned.m8n8.x4.shared.b16 {%0,%1,%2,%3}, [%4];"
                 : "=r"(r[0]), "=r"(r[1]), "=r"(r[2]), "=r"(r[3]) : "r"(addr));
}
__device__ __forceinline__ void ldsm4t(uint32_t* r, uint32_t addr) {
    asm volatile("ldmatrix.sync.aligned.m8n8.x4.trans.shared.b16 {%0,%1,%2,%3}, [%4];"
                 : "=r"(r[0]), "=r"(r[1]), "=r"(r[2]), "=r"(r[3]) : "r"(addr));
}
__device__ __forceinline__ void mma16816(float* c, const uint32_t* a, const uint32_t* b) {
    asm volatile(
        "mma.sync.aligned.m16n8k16.row.col.f32.f16.f16.f32 "
        "{%0,%1,%2,%3}, {%4,%5,%6,%7}, {%8,%9}, {%0,%1,%2,%3};"
        : "+f"(c[0]), "+f"(c[1]), "+f"(c[2]), "+f"(c[3])
        : "r"(a[0]), "r"(a[1]), "r"(a[2]), "r"(a[3]), "r"(b[0]), "r"(b[1]));
}
__device__ __forceinline__ uint32_t pack_h2(__half a, __half b) {
    __half2 t = __halves2half2(a, b);
    return *(uint32_t*)&t;
}
__device__ __forceinline__ uint32_t pack_f2h(float a, float b) {
    __half2 t = __halves2half2(__float2half_rn(a), __float2half_rn(b));
    return *(uint32_t*)&t;
}
// A-side split: h = fp16(x), m = fp16(h + 64*(x-h))
__device__ __forceinline__ void splitA(float f0, float f1, uint32_t& h, uint32_t& m) {
    __half h0 = __float2half_rn(f0), h1 = __float2half_rn(f1);
    float r0 = f0 - __half2float(h0), r1 = f1 - __half2float(h1);
    __half m0 = __float2half_rn(fmaf(64.f, r0, __half2float(h0)));
    __half m1 = __float2half_rn(fmaf(64.f, r1, __half2float(h1)));
    h = pack_h2(h0, h1);
    m = pack_h2(m0, m1);
}
// B-side split: h = fp16(x), m = fp16((x-h) + h/64)
__device__ __forceinline__ void splitB(float f0, float f1, uint32_t& h, uint32_t& m) {
    __half h0 = __float2half_rn(f0), h1 = __float2half_rn(f1);
    float r0 = f0 - __half2float(h0), r1 = f1 - __half2float(h1);
    __half m0 = __float2half_rn(fmaf(__half2float(h0), CINV64, r0));
    __half m1 = __float2half_rn(fmaf(__half2float(h1), CINV64, r1));
    h = pack_h2(h0, h1);
    m = pack_h2(m0, m1);
}

// ---------------------------------------------------------------------------
// Convert fp32 inputs -> fp16 h/m pairs. X: A-side. Weights: B-side.
// ---------------------------------------------------------------------------
__global__ __launch_bounds__(256) void convert_inputs(
    const float* __restrict__ X, const float* __restrict__ Wq,
    const float* __restrict__ Wk, const float* __restrict__ Wv,
    const float* __restrict__ Wo) {
    const int XQ = MROWS * DIM / 4;
    const int WQ = DIM * DIM / 4;
    const int total4 = XQ + 4 * WQ;
    for (int i = blockIdx.x * blockDim.x + threadIdx.x; i < total4;
         i += gridDim.x * blockDim.x) {
        const float* src;
        __half *dh, *dm;
        bool aside;
        if (i < XQ) {
            int e = i * 4;
            src = X + e; dh = gXh + e; dm = gXm + e; aside = true;
        } else {
            int t = i - XQ;
            int w = t / WQ;
            int off = (t - w * WQ) * 4;
            src = (w == 0) ? Wq + off : (w == 1) ? Wk + off
                  : (w == 2) ? Wv + off : Wo + off;
            dh = gWh + (size_t)w * DIM * DIM + off;
            dm = gWm + (size_t)w * DIM * DIM + off;
            aside = false;
        }
        float4 v = *(const float4*)src;
        uint32_t h0, m0, h1, m1;
        if (aside) {
            splitA(v.x, v.y, h0, m0);
            splitA(v.z, v.w, h1, m1);
        } else {
            splitB(v.x, v.y, h0, m0);
            splitB(v.z, v.w, h1, m1);
        }
        ((uint32_t*)dh)[0] = h0;
        ((uint32_t*)dh)[1] = h1;
        ((uint32_t*)dm)[0] = m0;
        ((uint32_t*)dm)[1] = m1;
    }
}

// ---------------------------------------------------------------------------
// Tensor-core GEMM. TERMS=2: merged 2-MMA (C = C1*63/64 + C2). TERMS=1:
// single fp16 MMA (C = Ah*Bh). 128x128 CTA tile, K-step 32, 8 warps
// (2m x 4n, 64x32 tiles), 3-stage cp.async.
// OMODE: 0=fp32 out(+bias), 1=splitA pair, 2=splitB pair, 3=single fp16.
// ---------------------------------------------------------------------------
#define STAGE_BYTES 32768
#define SM_BH 16384
#define SM_BM 24576
#define GEMM_SMEM (3 * STAGE_BYTES)

template <int TERMS>
__device__ __forceinline__ void gemm_fill(uint32_t sbuf,
                                          const __half* __restrict__ Ah,
                                          const __half* __restrict__ Am,
                                          const __half* __restrict__ Bh,
                                          const __half* __restrict__ Bm,
                                          int row0, int col0, int kt, int tid) {
    if (TERMS == 2) {
#pragma unroll
        for (int i = 0; i < 4; ++i) {  // A: 1024 chunks (h: c<4, m: c>=4)
            int lin = tid + i * 256;
            int m = lin >> 3, c = lin & 7;
            const __half* src =
                ((c < 4) ? Ah : Am) + (size_t)(row0 + m) * DIM + kt + (c & 3) * 8;
            cp16(sbuf + m * 128 + ((c ^ (m & 7)) << 4), src);
        }
#pragma unroll
        for (int i = 0; i < 4; ++i) {  // B: 1024 chunks (h + m)
            int lin = tid + i * 256;
            int tile = lin >> 9, rem = lin & 511;
            int k = rem >> 4, c = rem & 15;
            const __half* src =
                (tile ? Bm : Bh) + (size_t)(kt + k) * DIM + col0 + c * 8;
            cp16(sbuf + (tile ? SM_BM : SM_BH) + k * 256 +
                     ((c >> 3) << 7) + (((c & 7) ^ (k & 7)) << 4),
                 src);
        }
    } else {
#pragma unroll
        for (int i = 0; i < 2; ++i) {  // A: 512 chunks (hi only)
            int lin = tid + i * 256;
            int m = lin >> 2, c = lin & 3;
            const __half* src = Ah + (size_t)(row0 + m) * DIM + kt + c * 8;
            cp16(sbuf + m * 128 + ((c ^ (m & 7)) << 4), src);
        }
#pragma unroll
        for (int i = 0; i < 2; ++i) {  // B: 512 chunks (hi only)
            int lin = tid + i * 256;
            int k = lin >> 4, c = lin & 15;
            const __half* src = Bh + (size_t)(kt + k) * DIM + col0 + c * 8;
            cp16(sbuf + SM_BH + k * 256 + ((c >> 3) << 7) +
                     (((c & 7) ^ (k & 7)) << 4),
                 src);
        }
    }
}

template <int TERMS, int OMODE>
__device__ __forceinline__ void mma_gemm_body(
    const __half* __restrict__ Ah_g, const __half* __restrict__ Am_g,
    const __half* __restrict__ Bh_g, const __half* __restrict__ Bm_g,
    const float* __restrict__ bias, float* __restrict__ Yf,
    __half* __restrict__ Yh, __half* __restrict__ Ym) {
    extern __shared__ __align__(1024) char smem[];
    const uint32_t sb = smem_u32(smem);
    const int tid = threadIdx.x;
    const int row0 = blockIdx.y * 128, col0 = blockIdx.x * 128;
    const int lane = tid & 31, wid = tid >> 5;
    const int wm = wid & 1, wn = wid >> 1;
    const int q = lane >> 3, r = lane & 7;
    const int arow = (q & 1) * 8 + r;
    const int aq = q >> 1;

    float acc1[4][4][4], acc2[TERMS == 2 ? 4 : 1][TERMS == 2 ? 4 : 1][4];
#pragma unroll
    for (int mt = 0; mt < 4; ++mt)
#pragma unroll
        for (int nt = 0; nt < 4; ++nt)
#pragma unroll
            for (int e = 0; e < 4; ++e) acc1[mt][nt][e] = 0.f;
    if (TERMS == 2) {
#pragma unroll
        for (int mt = 0; mt < 4; ++mt)
#pragma unroll
            for (int nt = 0; nt < 4; ++nt)
#pragma unroll
                for (int e = 0; e < 4; ++e) acc2[mt][nt][e] = 0.f;
    }

    gemm_fill<TERMS>(sb, Ah_g, Am_g, Bh_g, Bm_g, row0, col0, 0, tid);
    cp_commit();
    gemm_fill<TERMS>(sb + STAGE_BYTES, Ah_g, Am_g, Bh_g, Bm_g, row0, col0, 32, tid);
    cp_commit();

    for (int s = 0; s < 32; ++s) {
        const int buf = s % 3;
        if (s + 2 < 32) {
            gemm_fill<TERMS>(sb + ((s + 2) % 3) * STAGE_BYTES, Ah_g, Am_g,
                             Bh_g, Bm_g, row0, col0, (s + 2) * 32, tid);
            cp_commit();
            asm volatile("cp.async.wait_group 2;" ::: "memory");
        } else if (s + 1 < 32) {
            asm volatile("cp.async.wait_group 1;" ::: "memory");
        } else {
            asm volatile("cp.async.wait_group 0;" ::: "memory");
        }
        __syncthreads();

        const uint32_t sA = sb + buf * STAGE_BYTES;
        const uint32_t sBh = sA + SM_BH;
        const uint32_t sBm = sA + SM_BM;

#pragma unroll
        for (int k16 = 0; k16 < 2; ++k16) {
            uint32_t bh[8], bm[8];
            {
                const int krow = k16 * 16 + (q & 1) * 8 + r;
#pragma unroll
                for (int g2 = 0; g2 < 2; ++g2) {
                    int cg = wn * 4 + g2 * 2 + (q >> 1);
                    uint32_t baddr = krow * 256 + ((cg >> 3) << 7) +
                                     (((cg & 7) ^ (krow & 7)) << 4);
                    ldsm4t(&bh[g2 * 4], sBh + baddr);
                    if (TERMS == 2) ldsm4t(&bm[g2 * 4], sBm + baddr);
                }
            }
            uint32_t ah[4][4];
#pragma unroll
            for (int mt = 0; mt < 4; ++mt) {
                int row = wm * 64 + mt * 16 + arow;
                int c1 = k16 * 2 + aq;
                ldsm4(ah[mt], sA + row * 128 + ((c1 ^ r) << 4));
            }
#pragma unroll
            for (int mt = 0; mt < 4; ++mt)
#pragma unroll
                for (int nt = 0; nt < 4; ++nt)
                    mma16816(acc1[mt][nt], ah[mt], &bh[(nt >> 1) * 4 + (nt & 1) * 2]);
            if (TERMS == 2) {
                uint32_t am[4][4];
#pragma unroll
                for (int mt = 0; mt < 4; ++mt) {
                    int row = wm * 64 + mt * 16 + arow;
                    int c2 = 4 + k16 * 2 + aq;
                    ldsm4(am[mt], sA + row * 128 + ((c2 ^ r) << 4));
                }
#pragma unroll
                for (int mt = 0; mt < 4; ++mt)
#pragma unroll
                    for (int nt = 0; nt < 4; ++nt)
                        mma16816(acc2[mt][nt], am[mt], &bm[(nt >> 1) * 4 + (nt & 1) * 2]);
            }
        }
        __syncthreads();
    }

    const int cg = lane >> 2, ct = lane & 3;
#pragma unroll
    for (int mt = 0; mt < 4; ++mt) {
        int r0 = row0 + wm * 64 + mt * 16 + cg;
#pragma unroll
        for (int nt = 0; nt < 4; ++nt) {
            int col = col0 + wn * 32 + nt * 8 + ct * 2;
            float b0 = bias ? bias[col] : 0.f;
            float b1 = bias ? bias[col + 1] : 0.f;
            float v00, v01, v10, v11;
            if (TERMS == 2) {
                v00 = fmaf(acc1[mt][nt][0], C63, acc2[mt][nt][0]) + b0;
                v01 = fmaf(acc1[mt][nt][1], C63, acc2[mt][nt][1]) + b1;
                v10 = fmaf(acc1[mt][nt][2], C63, acc2[mt][nt][2]) + b0;
                v11 = fmaf(acc1[mt][nt][3], C63, acc2[mt][nt][3]) + b1;
            } else {
                v00 = acc1[mt][nt][0] + b0;
                v01 = acc1[mt][nt][1] + b1;
                v10 = acc1[mt][nt][2] + b0;
                v11 = acc1[mt][nt][3] + b1;
            }
            if (OMODE == 0) {
                *(float2*)(Yf + (size_t)r0 * DIM + col) = make_float2(v00, v01);
                *(float2*)(Yf + (size_t)(r0 + 8) * DIM + col) = make_float2(v10, v11);
            } else if (OMODE == 3) {
                *(uint32_t*)&Yh[(size_t)r0 * DIM + col] = pack_f2h(v00, v01);
                *(uint32_t*)&Yh[(size_t)(r0 + 8) * DIM + col] = pack_f2h(v10, v11);
            } else {
                uint32_t h, m;
                if (OMODE == 1) splitA(v00, v01, h, m); else splitB(v00, v01, h, m);
                *(uint32_t*)&Yh[(size_t)r0 * DIM + col] = h;
                *(uint32_t*)&Ym[(size_t)r0 * DIM + col] = m;
                if (OMODE == 1) splitA(v10, v11, h, m); else splitB(v10, v11, h, m);
                *(uint32_t*)&Yh[(size_t)(r0 + 8) * DIM + col] = h;
                *(uint32_t*)&Ym[(size_t)(r0 + 8) * DIM + col] = m;
            }
        }
    }
}

__global__ __launch_bounds__(256, 1) void qkv_mma(const float* __restrict__ bq,
                                                  const float* __restrict__ bk) {
    const int z = blockIdx.z;
    const __half* Bh = gWh + (size_t)z * DIM * DIM;
    const __half* Bm = gWm + (size_t)z * DIM * DIM;
    if (z == 0) {
        mma_gemm_body<2, 1>(gXh, gXm, Bh, Bm, bq, nullptr, gQh, gQm);
    } else if (z == 1) {
        mma_gemm_body<2, 2>(gXh, gXm, Bh, Bm, bk, nullptr, gKh, gKm);
    } else {
        mma_gemm_body<1, 3>(gXh, nullptr, Bh, nullptr, nullptr, nullptr, gVh, nullptr);
    }
}

__global__ __launch_bounds__(256, 1) void out_mma(const float* __restrict__ bo,
                                                  float* __restrict__ out) {
    mma_gemm_body<1, 0>(gOh, nullptr, gWh + (size_t)3 * DIM * DIM, nullptr,
                        bo, out, nullptr, nullptr);
}

// ---------------------------------------------------------------------------
// Flash attention. QK^T: merged 2-MMA (logit accuracy). PV: single fp16 MMA.
// 8 warps; warp w owns 16 query rows. Hard causal (soft mask underflows).
// smem: Qh/Qm 32KB + 2 stages of {Kh,Km,Vh} 48KB.
// ---------------------------------------------------------------------------
#define A_ST0 32768
#define A_STAGE 49152
#define ATTN_SMEM (32768 + 2 * 49152)

__global__ __launch_bounds__(256, 1) void attn_mma() {
    extern __shared__ __align__(1024) char smem[];
    const uint32_t sb = smem_u32(smem);
    const int tid = threadIdx.x;
    const int lane = tid & 31, w = tid >> 5;
    const int q = lane >> 3, r = lane & 7;
    const int g = lane >> 2, t = lane & 3;
    const int it = 15 - (int)blockIdx.x;  // heavy tiles first
    const int bh = blockIdx.y;
    const int b = bh >> 4, h = bh & 15;
    const int i0 = it * 128;
    const float slope = exp2f(-0.5f * (float)(h + 1));
    const int qrow_base = b * SEQ + i0;
    const int hcol = h * HDIM;

    // ---- fill Q (h+m), 32KB ----
#pragma unroll
    for (int i = 0; i < 8; ++i) {
        int lin = tid + i * 256;
        int tz = lin >> 10;
        int rem = lin & 1023;
        int m = rem >> 3, c = rem & 7;
        const __half* src =
            (tz ? gQm : gQh) + (size_t)(qrow_base + m) * DIM + hcol + c * 8;
        cp16(sb + tz * 16384 + m * 128 + ((c ^ (m & 7)) << 4), src);
    }
    // ---- fill K/V stage 0: Kh, Km, Vh (48KB) ----
    {
        const int krow_base = b * SEQ;
#pragma unroll
        for (int i = 0; i < 12; ++i) {
            int lin = tid + i * 256;
            int tz = lin >> 10;  // 0=Kh 1=Km 2=Vh
            int rem = lin & 1023;
            int m = rem >> 3, c = rem & 7;
            const __half* src =
                ((tz == 0) ? gKh : (tz == 1) ? gKm : gVh) +
                (size_t)(krow_base + m) * DIM + hcol + c * 8;
            cp16(sb + A_ST0 + tz * 16384 + m * 128 + ((c ^ (m & 7)) << 4), src);
        }
    }
    cp_commit();

    float o[8][4];
#pragma unroll
    for (int nt = 0; nt < 8; ++nt)
#pragma unroll
        for (int e = 0; e < 4; ++e) o[nt][e] = 0.f;
    float m0 = -1e30f, m1 = -1e30f, l0 = 0.f, l1 = 0.f;
    uint32_t qh[4][4], qm[4][4];

    int buf = 0;
    for (int jt = 0; jt <= it; ++jt) {
        if (jt < it) {
            const int krow_base = b * SEQ + (jt + 1) * 128;
            const uint32_t st = sb + A_ST0 + (buf ^ 1) * A_STAGE;
#pragma unroll
            for (int i = 0; i < 12; ++i) {
                int lin = tid + i * 256;
                int tz = lin >> 10;
                int rem = lin & 1023;
                int m = rem >> 3, c = rem & 7;
                const __half* src =
                    ((tz == 0) ? gKh : (tz == 1) ? gKm : gVh) +
                    (size_t)(krow_base + m) * DIM + hcol + c * 8;
                cp16(st + tz * 16384 + m * 128 + ((c ^ (m & 7)) << 4), src);
            }
            cp_commit();
            asm volatile("cp.async.wait_group 1;" ::: "memory");
        } else {
            asm volatile("cp.async.wait_group 0;" ::: "memory");
        }
        __syncthreads();

        if (jt == 0) {  // hoist Q fragments
#pragma unroll
            for (int k16 = 0; k16 < 4; ++k16) {
                int row = w * 16 + (q & 1) * 8 + r;
                int c = k16 * 2 + (q >> 1);
                uint32_t ad = sb + row * 128 + ((c ^ r) << 4);
                ldsm4(qh[k16], ad);
                ldsm4(qm[k16], ad + 16384);
            }
        }

        const uint32_t sk = sb + A_ST0 + buf * A_STAGE;
        const uint32_t sv = sk + 32768;

        // ---- S = Q K^T (merged 2-MMA) ----
        float s[16][4];
#pragma unroll
        for (int nt16 = 0; nt16 < 8; ++nt16) {
            float s1[2][4], s2[2][4];
#pragma unroll
            for (int e = 0; e < 4; ++e) {
                s1[0][e] = s1[1][e] = 0.f;
                s2[0][e] = s2[1][e] = 0.f;
            }
            const int row = nt16 * 16 + (q >> 1) * 8 + r;
#pragma unroll
            for (int k16 = 0; k16 < 4; ++k16) {
                const int c = k16 * 2 + (q & 1);
                uint32_t ad = sk + row * 128 + ((c ^ r) << 4);
                uint32_t kh[4], km[4];
                ldsm4(kh, ad);
                ldsm4(km, ad + 16384);
                mma16816(s1[0], qh[k16], kh);
                mma16816(s2[0], qm[k16], km);
                mma16816(s1[1], qh[k16], kh + 2);
                mma16816(s2[1], qm[k16], km + 2);
            }
#pragma unroll
            for (int e = 0; e < 4; ++e) {
                s[2 * nt16][e] = fmaf(s1[0][e], C63, s2[0][e]);
                s[2 * nt16 + 1][e] = fmaf(s1[1][e], C63, s2[1][e]);
            }
        }

        // ---- online softmax ----
        const int j0 = jt * 128;
        const int rowg0 = i0 + w * 16 + g;
        const int rowg1 = rowg0 + 8;
        const bool diag = (jt == it);
        float mx0 = -1e30f, mx1 = -1e30f;
#pragma unroll
        for (int nt = 0; nt < 16; ++nt) {
            const int jc = j0 + nt * 8 + 2 * t;
            const float c0 = (float)jc;
            s[nt][0] = s[nt][0] * 0.125f - slope * c0;
            s[nt][1] = s[nt][1] * 0.125f - slope * (c0 + 1.f);
            s[nt][2] = s[nt][2] * 0.125f - slope * c0;
            s[nt][3] = s[nt][3] * 0.125f - slope * (c0 + 1.f);
            if (diag) {
                if (jc > rowg0) s[nt][0] = -1e30f;
                if (jc + 1 > rowg0) s[nt][1] = -1e30f;
                if (jc > rowg1) s[nt][2] = -1e30f;
                if (jc + 1 > rowg1) s[nt][3] = -1e30f;
            }
            mx0 = fmaxf(mx0, fmaxf(s[nt][0], s[nt][1]));
            mx1 = fmaxf(mx1, fmaxf(s[nt][2], s[nt][3]));
        }
        mx0 = fmaxf(mx0, __shfl_xor_sync(0xffffffffu, mx0, 1, 4));
        mx0 = fmaxf(mx0, __shfl_xor_sync(0xffffffffu, mx0, 2, 4));
        mx1 = fmaxf(mx1, __shfl_xor_sync(0xffffffffu, mx1, 1, 4));
        mx1 = fmaxf(mx1, __shfl_xor_sync(0xffffffffu, mx1, 2, 4));
        const float mn0 = fmaxf(m0, mx0), mn1 = fmaxf(m1, mx1);
        const float cr0 = __expf(m0 - mn0), cr1 = __expf(m1 - mn1);
        m0 = mn0;
        m1 = mn1;
        float sum0 = 0.f, sum1 = 0.f;
#pragma unroll
        for (int nt = 0; nt < 16; ++nt) {
            s[nt][0] = __expf(s[nt][0] - mn0);
            s[nt][1] = __expf(s[nt][1] - mn0);
            s[nt][2] = __expf(s[nt][2] - mn1);
            s[nt][3] = __expf(s[nt][3] - mn1);
            sum0 += s[nt][0] + s[nt][1];
            sum1 += s[nt][2] + s[nt][3];
        }
        sum0 += __shfl_xor_sync(0xffffffffu, sum0, 1, 4);
        sum0 += __shfl_xor_sync(0xffffffffu, sum0, 2, 4);
        sum1 += __shfl_xor_sync(0xffffffffu, sum1, 1, 4);
        sum1 += __shfl_xor_sync(0xffffffffu, sum1, 2, 4);
        l0 = l0 * cr0 + sum0;
        l1 = l1 * cr1 + sum1;
#pragma unroll
        for (int nt = 0; nt < 8; ++nt) {
            o[nt][0] *= cr0;
            o[nt][1] *= cr0;
            o[nt][2] *= cr1;
            o[nt][3] *= cr1;
        }

        // ---- O += P V (single fp16 MMA) ----
#pragma unroll
        for (int k16 = 0; k16 < 8; ++k16) {
            uint32_t ph[4];
            ph[0] = pack_f2h(s[2 * k16][0], s[2 * k16][1]);
            ph[1] = pack_f2h(s[2 * k16][2], s[2 * k16][3]);
            ph[2] = pack_f2h(s[2 * k16 + 1][0], s[2 * k16 + 1][1]);
            ph[3] = pack_f2h(s[2 * k16 + 1][2], s[2 * k16 + 1][3]);
            const int row = k16 * 16 + (q & 1) * 8 + r;
#pragma unroll
            for (int cgp = 0; cgp < 4; ++cgp) {
                const int c = cgp * 2 + (q >> 1);
                uint32_t ad = sv + row * 128 + ((c ^ r) << 4);
                uint32_t vh[4];
                ldsm4t(vh, ad);
                mma16816(o[cgp * 2], ph, vh);
                mma16816(o[cgp * 2 + 1], ph, vh + 2);
            }
        }
        __syncthreads();
        buf ^= 1;
    }

    // ---- epilogue: normalize, store single fp16 ----
    const float inv0 = 1.f / l0, inv1 = 1.f / l1;
    const size_t orow0 = (size_t)(qrow_base + w * 16 + g) * DIM + hcol;
    const size_t orow1 = orow0 + (size_t)8 * DIM;
#pragma unroll
    for (int nt = 0; nt < 8; ++nt) {
        const int col = nt * 8 + 2 * t;
        *(uint32_t*)&gOh[orow0 + col] = pack_f2h(o[nt][0] * inv0, o[nt][1] * inv0);
        *(uint32_t*)&gOh[orow1 + col] = pack_f2h(o[nt][2] * inv1, o[nt][3] * inv1);
    }
}

// ---------------------------------------------------------------------------
extern "C" void kernel_launch(void* const* d_in, const int* in_sizes, int n_in,
                              void* d_out, int out_size) {
    const float* X  = (const float*)d_in[0];
    const float* Wq = (const float*)d_in[1];
    const float* bq = (const float*)d_in[2];
    const float* Wk = (const float*)d_in[3];
    const float* bk = (const float*)d_in[4];
    const float* Wv = (const float*)d_in[5];
    const float* Wo = (const float*)d_in[6];
    const float* bo = (const float*)d_in[7];
    float* out = (float*)d_out;

    cudaFuncSetAttribute(qkv_mma, cudaFuncAttributeMaxDynamicSharedMemorySize, GEMM_SMEM);
    cudaFuncSetAttribute(out_mma, cudaFuncAttributeMaxDynamicSharedMemorySize, GEMM_SMEM);
    cudaFuncSetAttribute(attn_mma, cudaFuncAttributeMaxDynamicSharedMemorySize, ATTN_SMEM);

    convert_inputs<<<2048, 256>>>(X, Wq, Wk, Wv, Wo);
    qkv_mma<<<dim3(DIM / 128, MROWS / 128, 3), 256, GEMM_SMEM>>>(bq, bk);
    attn_mma<<<dim3(SEQ / 128, BQ * NH), 256, ATTN_SMEM>>>();
    out_mma<<<dim3(DIM / 128, MROWS / 128, 1), 256, GEMM_SMEM>>>(bo, out);
}